// round 9
// baseline (speedup 1.0000x reference)
#include <cuda_runtime.h>
#include <math.h>

#define N_USERS 50000
#define N_ITEMS 100000
#define NN      150000
#define DD      64
#define NI      128
#define TS      32
#define TEMP    0.2f
#define KL_REG  0.01f
#define EMB_REG 1e-5f
#define INT_REG 1e-5f
#define SSL_REG 0.1f
#define BB      4096
#define E_TOT   3150000
#define NSPLIT  16
#define JCH     (BB / NSPLIT)

#define SCAN_CHUNK 1024
#define NBLK_SCAN  ((NN + SCAN_CHUNK - 1) / SCAN_CHUNK)   // 147

// ---------------- scratch (device globals; no allocation allowed) ------------
__device__ int   g_deg[NN];
__device__ float g_dinv[NN];
__device__ int   g_rowptr[NN + 1];
__device__ int   g_cursor[NN];
__device__ int   g_blocksum[NBLK_SCAN];
__device__ int   g_blockoff[NBLK_SCAN];
__device__ __align__(16) int2  g_csr[E_TOT];         // .x = target, .y = weight bits
__device__ __align__(16) float g_cur[(size_t)NN * DD];
__device__ __align__(16) float g_nxt[(size_t)NN * DD];
__device__ __align__(16) float g_acc[(size_t)NN * DD];
__device__ __align__(16) float g_ugen[BB * DD];
__device__ __align__(16) float g_uintn[BB * DD];
__device__ __align__(16) float g_igen[BB * DD];
__device__ __align__(16) float g_iintn[BB * DD];
__device__ float g_neg[2 * BB];
__device__ float g_pos[2 * BB];
__device__ float g_sums[8];   // 0:bpr 1:kl 2:emb 3:int 4:cl

// ---------------- helpers ----------------------------------------------------
__device__ __forceinline__ float softplusf(float x) {
    return x > 0.f ? x + log1pf(expf(-x)) : log1pf(expf(x));
}

__device__ __forceinline__ unsigned long long fma2(unsigned long long a,
                                                   unsigned long long b,
                                                   unsigned long long c) {
    unsigned long long d;
    asm("fma.rn.f32x2 %0, %1, %2, %3;" : "=l"(d) : "l"(a), "l"(b), "l"(c));
    return d;
}

__device__ __forceinline__ float blkSum256(float v) {
    __shared__ float sp[8];
    int lane = threadIdx.x & 31, wid = threadIdx.x >> 5;
#pragma unroll
    for (int o = 16; o; o >>= 1) v += __shfl_down_sync(0xffffffffu, v, o);
    if (lane == 0) sp[wid] = v;
    __syncthreads();
    v = (threadIdx.x < 8) ? sp[threadIdx.x] : 0.f;
    if (wid == 0) {
#pragma unroll
        for (int o = 4; o; o >>= 1) v += __shfl_down_sync(0xffffffffu, v, o);
    }
    __syncthreads();
    return v;
}

__device__ __forceinline__ int blkSum256i(int v) {
    __shared__ int sp[8];
    int lane = threadIdx.x & 31, wid = threadIdx.x >> 5;
#pragma unroll
    for (int o = 16; o; o >>= 1) v += __shfl_down_sync(0xffffffffu, v, o);
    if (lane == 0) sp[wid] = v;
    __syncthreads();
    v = (threadIdx.x < 8) ? sp[threadIdx.x] : 0;
    if (wid == 0) {
#pragma unroll
        for (int o = 4; o; o >>= 1) v += __shfl_down_sync(0xffffffffu, v, o);
    }
    __syncthreads();
    return v;
}

__device__ __forceinline__ float blkSum128(float v, float* partial) {
    int lane = threadIdx.x & 31, wid = threadIdx.x >> 5;
#pragma unroll
    for (int o = 16; o; o >>= 1) v += __shfl_down_sync(0xffffffffu, v, o);
    if (lane == 0) partial[wid] = v;
    __syncthreads();
    float s = partial[0] + partial[1] + partial[2] + partial[3];
    __syncthreads();
    return s;
}

__device__ __forceinline__ float blkMax128(float v, float* partial) {
    int lane = threadIdx.x & 31, wid = threadIdx.x >> 5;
#pragma unroll
    for (int o = 16; o; o >>= 1) v = fmaxf(v, __shfl_down_sync(0xffffffffu, v, o));
    if (lane == 0) partial[wid] = v;
    __syncthreads();
    float s = fmaxf(fmaxf(partial[0], partial[1]), fmaxf(partial[2], partial[3]));
    __syncthreads();
    return s;
}

// ---------------- kernels ----------------------------------------------------
__global__ void k_clear() {
    int i = blockIdx.x * blockDim.x + threadIdx.x;
    if (i < NN) g_deg[i] = 0;
    if (i < 8) g_sums[i] = 0.f;
    if (i < 2 * BB) { g_neg[i] = 0.f; g_pos[i] = 0.f; }
}

__global__ void k_deg(const int* __restrict__ hl, int E) {
    int e = blockIdx.x * blockDim.x + threadIdx.x;
    if (e < E) atomicAdd(&g_deg[hl[e]], 1);
}

// chunk reduce + dinv fused. grid NBLK_SCAN, block 256
__global__ void k_scanA() {
    int base = blockIdx.x * SCAN_CHUNK;
    int v = 0;
    for (int i = threadIdx.x; i < SCAN_CHUNK; i += 256) {
        int idx = base + i;
        if (idx < NN) {
            int d = g_deg[idx];
            v += d;
            g_dinv[idx] = rsqrtf((float)d);
        }
    }
    int tot = blkSum256i(v);
    if (threadIdx.x == 0) g_blocksum[blockIdx.x] = tot;
}

// single-warp shuffle scan of 147 partials (5 values/lane)
__global__ void k_scanB() {
    int lane = threadIdx.x;
    int v[5]; int s = 0;
#pragma unroll
    for (int j = 0; j < 5; j++) {
        int i = lane * 5 + j;
        v[j] = (i < NBLK_SCAN) ? g_blocksum[i] : 0;
        s += v[j];
    }
    int t = s;
#pragma unroll
    for (int o = 1; o < 32; o <<= 1) {
        int x = __shfl_up_sync(0xffffffffu, t, o);
        if (lane >= o) t += x;
    }
    int run = t - s;
#pragma unroll
    for (int j = 0; j < 5; j++) {
        int i = lane * 5 + j;
        if (i < NBLK_SCAN) g_blockoff[i] = run;
        run += v[j];
    }
    if (lane == 31) g_rowptr[NN] = t;
}

// grid NBLK_SCAN, block 256, 4 elems/thread (256*4 = 1024 = SCAN_CHUNK)
__global__ void k_scanC() {
    __shared__ int wsum[8];
    int base = blockIdx.x * SCAN_CHUNK;
    int tid = threadIdx.x, lane = tid & 31, wid = tid >> 5;
    int v[4]; int s = 0;
#pragma unroll
    for (int j = 0; j < 4; j++) {
        int i = base + tid * 4 + j;
        v[j] = (i < NN) ? g_deg[i] : 0;
        s += v[j];
    }
    int t = s;
#pragma unroll
    for (int o = 1; o < 32; o <<= 1) {
        int x = __shfl_up_sync(0xffffffffu, t, o);
        if (lane >= o) t += x;
    }
    if (lane == 31) wsum[wid] = t;
    __syncthreads();
    if (wid == 0 && lane < 8) {
        int w = wsum[lane];
#pragma unroll
        for (int o = 1; o < 8; o <<= 1) {
            int x = __shfl_up_sync(0xffu, w, o);
            if (lane >= o) w += x;
        }
        wsum[lane] = w;
    }
    __syncthreads();
    int run = g_blockoff[blockIdx.x] + ((wid > 0) ? wsum[wid - 1] : 0) + (t - s);
#pragma unroll
    for (int j = 0; j < 4; j++) {
        int i = base + tid * 4 + j;
        if (i < NN) { g_rowptr[i] = run; g_cursor[i] = run; }
        run += v[j];
    }
}

__global__ void k_scatter(const int* __restrict__ hl, const int* __restrict__ tl, int E) {
    int e = blockIdx.x * blockDim.x + threadIdx.x;
    if (e >= E) return;
    int h = hl[e], t = tl[e];
    int idx = atomicAdd(&g_cursor[h], 1);
    g_csr[idx] = make_int2(t, __float_as_int(g_dinv[h] * g_dinv[t]));
}

__global__ void k_init(const float* __restrict__ ue, const float* __restrict__ ie) {
    int i = blockIdx.x * blockDim.x + threadIdx.x;
    if (i >= NN * (DD / 2)) return;
    int n = i >> 5, h = i & 31;
    const float* src = (n < N_USERS) ? (ue + (size_t)n * DD) : (ie + (size_t)(n - N_USERS) * DD);
    float2 v = make_float2(src[h * 2], src[h * 2 + 1]);
    ((float2*)g_cur)[i] = v;
    ((float2*)g_acc)[i] = v;
}

// one warp per node; lane handles 2 dims (float2); int2 CSR; 8-edge unroll.
__global__ void k_prop(const float* __restrict__ src, float* __restrict__ dst) {
    int gw = (blockIdx.x * blockDim.x + threadIdx.x) >> 5;
    int lane = threadIdx.x & 31;
    if (gw >= NN) return;
    int s = g_rowptr[gw], e = g_rowptr[gw + 1];
    float a0 = 0.f, a1 = 0.f;
    int k = s;
    int lo = lane * 2;
    for (; k + 7 < e; k += 8) {
        int2 e0 = __ldg(&g_csr[k]),     e1 = __ldg(&g_csr[k + 1]);
        int2 e2 = __ldg(&g_csr[k + 2]), e3 = __ldg(&g_csr[k + 3]);
        int2 e4 = __ldg(&g_csr[k + 4]), e5 = __ldg(&g_csr[k + 5]);
        int2 e6 = __ldg(&g_csr[k + 6]), e7 = __ldg(&g_csr[k + 7]);
        float2 v0 = __ldg((const float2*)(src + (size_t)e0.x * DD + lo));
        float2 v1 = __ldg((const float2*)(src + (size_t)e1.x * DD + lo));
        float2 v2 = __ldg((const float2*)(src + (size_t)e2.x * DD + lo));
        float2 v3 = __ldg((const float2*)(src + (size_t)e3.x * DD + lo));
        float2 v4 = __ldg((const float2*)(src + (size_t)e4.x * DD + lo));
        float2 v5 = __ldg((const float2*)(src + (size_t)e5.x * DD + lo));
        float2 v6 = __ldg((const float2*)(src + (size_t)e6.x * DD + lo));
        float2 v7 = __ldg((const float2*)(src + (size_t)e7.x * DD + lo));
        float w0 = __int_as_float(e0.y), w1 = __int_as_float(e1.y);
        float w2 = __int_as_float(e2.y), w3 = __int_as_float(e3.y);
        float w4 = __int_as_float(e4.y), w5 = __int_as_float(e5.y);
        float w6 = __int_as_float(e6.y), w7 = __int_as_float(e7.y);
        a0 += w0 * v0.x + w1 * v1.x + w2 * v2.x + w3 * v3.x
            + w4 * v4.x + w5 * v5.x + w6 * v6.x + w7 * v7.x;
        a1 += w0 * v0.y + w1 * v1.y + w2 * v2.y + w3 * v3.y
            + w4 * v4.y + w5 * v5.y + w6 * v6.y + w7 * v7.y;
    }
    for (; k < e; k++) {
        int2 ed = __ldg(&g_csr[k]);
        float2 v = __ldg((const float2*)(src + (size_t)ed.x * DD + lo));
        float w = __int_as_float(ed.y);
        a0 += w * v.x;
        a1 += w * v.y;
    }
    size_t o = (size_t)gw * DD + lo;
    ((float2*)(dst + o))[0] = make_float2(a0, a1);
    float2* ap = (float2*)(g_acc + o);
    float2 av = *ap;
    av.x += a0; av.y += a1;
    *ap = av;
}

// KL term over all N rows. block = 256 = 4 rows x 64 dims.
__global__ void k_kl(const float* __restrict__ lw, const float* __restrict__ lb) {
    __shared__ float swT[TS * DD];   // transposed lin_w: swT[t*64+d]
    __shared__ float sb[DD];
    __shared__ float ss[4][TS];
    int tid = threadIdx.x;
    for (int i = tid; i < TS * DD; i += 256) {
        int d = i >> 5, t = i & 31;
        swT[t * DD + d] = lw[i];
    }
    if (tid < DD) sb[tid] = lb[tid];
    __syncthreads();
    int r = tid >> 6;
    int d = tid & 63;
    int row = blockIdx.x * 4 + r;
    if (row < NN && d < TS) ss[r][d] = softplusf(g_acc[(size_t)row * DD + d]);
    __syncthreads();
    float klv = 0.f;
    if (row < NN) {
        float stdv = sb[d] + 1e-8f;
#pragma unroll
        for (int t = 0; t < TS; t++) stdv += ss[r][t] * swT[t * DD + d];
        float mn = g_acc[(size_t)row * DD + d];
        float kl = -0.5f * (1.f + 2.f * stdv - mn * mn - expf(2.f * stdv));
        if (isfinite(kl)) klv = kl;
    }
    float tot = blkSum256(klv);
    if (tid == 0) atomicAdd(&g_sums[1], tot);
}

// BPR + embedding-reg over B samples; one warp per sample.
__global__ void k_bpr(const float* __restrict__ ue, const float* __restrict__ ie,
                      const int* __restrict__ users, const int* __restrict__ pos,
                      const int* __restrict__ neg) {
    int w = (blockIdx.x * blockDim.x + threadIdx.x) >> 5;
    int lane = threadIdx.x & 31;
    if (w >= BB) return;
    int u = users[w], p = pos[w], n = neg[w];
    const float* au = g_acc + (size_t)u * DD;
    const float* ap = g_acc + (size_t)(N_USERS + p) * DD;
    const float* an = g_acc + (size_t)(N_USERS + n) * DD;
    float ps = 0.f, ns = 0.f, es = 0.f;
#pragma unroll
    for (int j = 0; j < 2; j++) {
        int d = lane + 32 * j;
        float x = au[d];
        ps += x * ap[d];
        ns += x * an[d];
        float a = ue[(size_t)u * DD + d], b = ie[(size_t)p * DD + d], c = ie[(size_t)n * DD + d];
        es += a * a + b * b + c * c;
    }
#pragma unroll
    for (int o = 16; o; o >>= 1) {
        ps += __shfl_down_sync(0xffffffffu, ps, o);
        ns += __shfl_down_sync(0xffffffffu, ns, o);
        es += __shfl_down_sync(0xffffffffu, es, o);
    }
    if (lane == 0) {
        atomicAdd(&g_sums[0], softplusf(ns - ps));
        atomicAdd(&g_sums[2], es);
    }
}

// intent regularizer
__global__ void k_intreg(const float* __restrict__ ui, const float* __restrict__ ii) {
    int i = blockIdx.x * blockDim.x + threadIdx.x;
    float v = 0.f;
    if (i < DD * NI)            { float a = ui[i];           v = a * a; }
    else if (i < 2 * DD * NI)   { float a = ii[i - DD * NI]; v = a * a; }
    float tot = blkSum256(v);
    if (threadIdx.x == 0) atomicAdd(&g_sums[3], tot);
}

// per-sample features: normalized gen_emb and intent-projection rows.
__global__ void k_sample(const float* __restrict__ lw, const float* __restrict__ lb,
                         const float* __restrict__ eps,
                         const float* __restrict__ uintm, const float* __restrict__ iintm,
                         const int* __restrict__ users, const int* __restrict__ pos) {
    __shared__ float mrow[DD];
    __shared__ float sp[TS];
    __shared__ float prob[NI];
    __shared__ float partial[4];
    int b = blockIdx.x & (BB - 1);
    int side = blockIdx.x >> 12;
    int tid = threadIdx.x;
    int node = side ? (N_USERS + pos[b]) : users[b];
    const float* intent = side ? iintm : uintm;
    float* outgen = side ? g_igen : g_ugen;
    float* outint = side ? g_iintn : g_uintn;

    if (tid < DD) mrow[tid] = g_acc[(size_t)node * DD + tid];
    __syncthreads();
    if (tid < TS) sp[tid] = softplusf(mrow[tid]);
    __syncthreads();

    float genv = 0.f;
    if (tid < DD) {
        float stdv = lb[tid] + 1e-8f;
#pragma unroll
        for (int t = 0; t < TS; t++) stdv += sp[t] * lw[tid * TS + t];
        genv = mrow[tid] + eps[(size_t)node * DD + tid] * stdv;
    }
    float gn2 = blkSum128(genv * genv, partial);
    if (tid < DD) outgen[b * DD + tid] = genv * rsqrtf(gn2);

    float lg = 0.f;
#pragma unroll
    for (int d = 0; d < DD; d++) lg += mrow[d] * intent[d * NI + tid];
    float mx = blkMax128(lg, partial);
    float ev = expf(lg - mx);
    float ssum = blkSum128(ev, partial);
    prob[tid] = ev;
    __syncthreads();

    float o = 0.f;
    if (tid < DD) {
        const float4* ip = (const float4*)(intent + tid * NI);
        const float4* pp = (const float4*)prob;
#pragma unroll
        for (int k = 0; k < NI / 4; k++) {
            float4 a = ip[k], pq = pp[k];
            o += a.x * pq.x + a.y * pq.y + a.z * pq.z + a.w * pq.w;
        }
        o /= ssum;
    }
    float on2 = blkSum128(o * o, partial);
    if (tid < DD) outint[b * DD + tid] = o * rsqrtf(on2);
}

// InfoNCE partial sums with packed f32x2 FMA: grid (BB/256, NSPLIT).
__global__ void k_nce(const float* __restrict__ e1, const float* __restrict__ e2,
                      float* __restrict__ negbuf, float* __restrict__ posbuf) {
    __shared__ __align__(16) float tile[32][DD];
    int tid = threadIdx.x;
    int i = blockIdx.x * 256 + tid;
    unsigned long long r2[DD / 2];
    {
        const unsigned long long* rp = (const unsigned long long*)(e1 + (size_t)i * DD);
#pragma unroll
        for (int k = 0; k < DD / 2; k++) r2[k] = rp[k];
    }
    float negs = 0.f, pos = 0.f;
    int j0 = blockIdx.y * JCH;
    for (int jt = 0; jt < JCH; jt += 32) {
#pragma unroll
        for (int q = 0; q < 8; q++) {
            int idx = tid + q * 256;
            tile[idx >> 6][idx & 63] = e2[(size_t)(j0 + jt) * DD + idx];
        }
        __syncthreads();
#pragma unroll 2
        for (int jj = 0; jj < 32; jj++) {
            const unsigned long long* trow = (const unsigned long long*)tile[jj];
            unsigned long long acc2 = 0ull;   // packed {0.f, 0.f}
#pragma unroll
            for (int k = 0; k < DD / 2; k++) acc2 = fma2(r2[k], trow[k], acc2);
            float lo, hi;
            asm("mov.b64 {%0, %1}, %2;" : "=f"(lo), "=f"(hi) : "l"(acc2));
            float dot = lo + hi;
            float evv = __expf(dot * (1.f / TEMP));
            negs += evv;
            if (j0 + jt + jj == i) pos = evv;
        }
        __syncthreads();
    }
    atomicAdd(&negbuf[i], negs);
    if (i >= j0 && i < j0 + JCH) posbuf[i] = pos;
}

// fused nce-final + output (single block of 256)
__global__ void k_final(float* __restrict__ out) {
    int tid = threadIdx.x;
    float cl = 0.f;
    for (int i = tid; i < 2 * BB; i += 256)
        cl += -logf(g_pos[i] / (g_neg[i] + 1e-8f) + 1e-8f);
    float cltot = blkSum256(cl);
    if (tid == 0) {
        float bpr = g_sums[0] / (float)BB;
        float kl  = KL_REG * (g_sums[1] / (float)NN);
        out[0] = bpr + kl;
        out[1] = SSL_REG * (cltot / (float)BB);
        out[2] = EMB_REG * g_sums[2];
        out[3] = INT_REG * g_sums[3];
    }
}

// ---------------- launch ------------------------------------------------------
extern "C" void kernel_launch(void* const* d_in, const int* in_sizes, int n_in,
                              void* d_out, int out_size) {
    const float* user_emb = (const float*)d_in[0];
    const float* item_emb = (const float*)d_in[1];
    const float* uintm    = (const float*)d_in[2];
    const float* iintm    = (const float*)d_in[3];
    const float* lw       = (const float*)d_in[4];
    const float* lb       = (const float*)d_in[5];
    const float* eps      = (const float*)d_in[6];
    const int*   hl       = (const int*)d_in[7];
    const int*   tl       = (const int*)d_in[8];
    const int*   users    = (const int*)d_in[9];
    const int*   pos      = (const int*)d_in[10];
    const int*   neg      = (const int*)d_in[11];
    int E = in_sizes[7];
    float* out = (float*)d_out;

    void *p_cur, *p_nxt, *p_ugen, *p_uint, *p_igen, *p_iint, *p_neg, *p_pos;
    cudaGetSymbolAddress(&p_cur, g_cur);
    cudaGetSymbolAddress(&p_nxt, g_nxt);
    cudaGetSymbolAddress(&p_ugen, g_ugen);
    cudaGetSymbolAddress(&p_uint, g_uintn);
    cudaGetSymbolAddress(&p_igen, g_igen);
    cudaGetSymbolAddress(&p_iint, g_iintn);
    cudaGetSymbolAddress(&p_neg,  g_neg);
    cudaGetSymbolAddress(&p_pos,  g_pos);

    k_clear<<<(NN + 255) / 256, 256>>>();
    k_deg<<<(E + 255) / 256, 256>>>(hl, E);
    k_scanA<<<NBLK_SCAN, 256>>>();
    k_scanB<<<1, 32>>>();
    k_scanC<<<NBLK_SCAN, 256>>>();
    k_scatter<<<(E + 255) / 256, 256>>>(hl, tl, E);
    k_init<<<(NN * (DD / 2) + 255) / 256, 256>>>(user_emb, item_emb);

    k_prop<<<(NN * 32 + 255) / 256, 256>>>((const float*)p_cur, (float*)p_nxt);
    k_prop<<<(NN * 32 + 255) / 256, 256>>>((const float*)p_nxt, (float*)p_cur);
    k_prop<<<(NN * 32 + 255) / 256, 256>>>((const float*)p_cur, (float*)p_nxt);

    k_kl<<<(NN + 3) / 4, 256>>>(lw, lb);
    k_bpr<<<(BB * 32 + 255) / 256, 256>>>(user_emb, item_emb, users, pos, neg);
    k_intreg<<<(2 * DD * NI + 255) / 256, 256>>>(uintm, iintm);
    k_sample<<<2 * BB, 128>>>(lw, lb, eps, uintm, iintm, users, pos);

    {
        dim3 grid(BB / 256, NSPLIT);
        k_nce<<<grid, 256>>>((const float*)p_ugen, (const float*)p_uint,
                             (float*)p_neg, (float*)p_pos);
        k_nce<<<grid, 256>>>((const float*)p_igen, (const float*)p_iint,
                             (float*)p_neg + BB, (float*)p_pos + BB);
    }
    k_final<<<1, 256>>>(out);
}

// round 10
// speedup vs baseline: 1.5690x; 1.5690x over previous
#include <cuda_runtime.h>
#include <math.h>

#define N_USERS 50000
#define N_ITEMS 100000
#define NN      150000
#define DD      64
#define NI      128
#define TS      32
#define TEMP    0.2f
#define KL_REG  0.01f
#define EMB_REG 1e-5f
#define INT_REG 1e-5f
#define SSL_REG 0.1f
#define BB      4096
#define E_TOT   3150000
#define NSPLIT  16
#define JCH     (BB / NSPLIT)

#define SCAN_CHUNK 1024
#define NBLK_SCAN  ((NN + SCAN_CHUNK - 1) / SCAN_CHUNK)   // 147

// ---------------- scratch (device globals; no allocation allowed) ------------
__device__ int   g_deg[NN];
__device__ float g_dinv[NN];
__device__ int   g_rowptr[NN + 1];
__device__ int   g_cursor[NN];
__device__ int   g_blocksum[NBLK_SCAN];
__device__ int   g_blockoff[NBLK_SCAN];
__device__ int   g_csr_t[E_TOT];
__device__ float g_csr_g[E_TOT];
__device__ __align__(16) float g_cur[(size_t)NN * DD];
__device__ __align__(16) float g_nxt[(size_t)NN * DD];
__device__ __align__(16) float g_acc[(size_t)NN * DD];
__device__ __align__(16) float g_ugen[BB * DD];
__device__ __align__(16) float g_uintn[BB * DD];
__device__ __align__(16) float g_igen[BB * DD];
__device__ __align__(16) float g_iintn[BB * DD];
__device__ float g_neg[2 * BB];
__device__ float g_pos[2 * BB];
__device__ float g_sums[8];   // 0:bpr 1:kl 2:emb 3:int 4:cl

// ---------------- helpers ----------------------------------------------------
__device__ __forceinline__ float softplusf(float x) {
    return x > 0.f ? x + log1pf(expf(-x)) : log1pf(expf(x));
}

__device__ __forceinline__ float blkSum256(float v) {
    __shared__ float sp[8];
    int lane = threadIdx.x & 31, wid = threadIdx.x >> 5;
#pragma unroll
    for (int o = 16; o; o >>= 1) v += __shfl_down_sync(0xffffffffu, v, o);
    if (lane == 0) sp[wid] = v;
    __syncthreads();
    v = (threadIdx.x < 8) ? sp[threadIdx.x] : 0.f;
    if (wid == 0) {
#pragma unroll
        for (int o = 4; o; o >>= 1) v += __shfl_down_sync(0xffffffffu, v, o);
    }
    __syncthreads();
    return v;
}

__device__ __forceinline__ int blkSum256i(int v) {
    __shared__ int sp[8];
    int lane = threadIdx.x & 31, wid = threadIdx.x >> 5;
#pragma unroll
    for (int o = 16; o; o >>= 1) v += __shfl_down_sync(0xffffffffu, v, o);
    if (lane == 0) sp[wid] = v;
    __syncthreads();
    v = (threadIdx.x < 8) ? sp[threadIdx.x] : 0;
    if (wid == 0) {
#pragma unroll
        for (int o = 4; o; o >>= 1) v += __shfl_down_sync(0xffffffffu, v, o);
    }
    __syncthreads();
    return v;
}

__device__ __forceinline__ float blkSum128(float v, float* partial) {
    int lane = threadIdx.x & 31, wid = threadIdx.x >> 5;
#pragma unroll
    for (int o = 16; o; o >>= 1) v += __shfl_down_sync(0xffffffffu, v, o);
    if (lane == 0) partial[wid] = v;
    __syncthreads();
    float s = partial[0] + partial[1] + partial[2] + partial[3];
    __syncthreads();
    return s;
}

__device__ __forceinline__ float blkMax128(float v, float* partial) {
    int lane = threadIdx.x & 31, wid = threadIdx.x >> 5;
#pragma unroll
    for (int o = 16; o; o >>= 1) v = fmaxf(v, __shfl_down_sync(0xffffffffu, v, o));
    if (lane == 0) partial[wid] = v;
    __syncthreads();
    float s = fmaxf(fmaxf(partial[0], partial[1]), fmaxf(partial[2], partial[3]));
    __syncthreads();
    return s;
}

// ---------------- kernels ----------------------------------------------------
__global__ void k_clear() {
    int i = blockIdx.x * blockDim.x + threadIdx.x;
    if (i < NN) g_deg[i] = 0;
    if (i < 8) g_sums[i] = 0.f;
    if (i < 2 * BB) { g_neg[i] = 0.f; g_pos[i] = 0.f; }
}

__global__ void k_deg(const int* __restrict__ hl, int E) {
    int e = blockIdx.x * blockDim.x + threadIdx.x;
    if (e < E) atomicAdd(&g_deg[hl[e]], 1);
}

// chunk reduce + dinv fused. grid NBLK_SCAN, block 256
__global__ void k_scanA() {
    int base = blockIdx.x * SCAN_CHUNK;
    int v = 0;
    for (int i = threadIdx.x; i < SCAN_CHUNK; i += 256) {
        int idx = base + i;
        if (idx < NN) {
            int d = g_deg[idx];
            v += d;
            g_dinv[idx] = rsqrtf((float)d);
        }
    }
    int tot = blkSum256i(v);
    if (threadIdx.x == 0) g_blocksum[blockIdx.x] = tot;
}

// single-warp shuffle scan of 147 partials (5 values/lane)
__global__ void k_scanB() {
    int lane = threadIdx.x;
    int v[5]; int s = 0;
#pragma unroll
    for (int j = 0; j < 5; j++) {
        int i = lane * 5 + j;
        v[j] = (i < NBLK_SCAN) ? g_blocksum[i] : 0;
        s += v[j];
    }
    int t = s;
#pragma unroll
    for (int o = 1; o < 32; o <<= 1) {
        int x = __shfl_up_sync(0xffffffffu, t, o);
        if (lane >= o) t += x;
    }
    int run = t - s;
#pragma unroll
    for (int j = 0; j < 5; j++) {
        int i = lane * 5 + j;
        if (i < NBLK_SCAN) g_blockoff[i] = run;
        run += v[j];
    }
    if (lane == 31) g_rowptr[NN] = t;
}

// grid NBLK_SCAN, block 256, 4 elems/thread (256*4 = 1024 = SCAN_CHUNK)
__global__ void k_scanC() {
    __shared__ int wsum[8];
    int base = blockIdx.x * SCAN_CHUNK;
    int tid = threadIdx.x, lane = tid & 31, wid = tid >> 5;
    int v[4]; int s = 0;
#pragma unroll
    for (int j = 0; j < 4; j++) {
        int i = base + tid * 4 + j;
        v[j] = (i < NN) ? g_deg[i] : 0;
        s += v[j];
    }
    int t = s;
#pragma unroll
    for (int o = 1; o < 32; o <<= 1) {
        int x = __shfl_up_sync(0xffffffffu, t, o);
        if (lane >= o) t += x;
    }
    if (lane == 31) wsum[wid] = t;
    __syncthreads();
    if (wid == 0 && lane < 8) {
        int w = wsum[lane];
#pragma unroll
        for (int o = 1; o < 8; o <<= 1) {
            int x = __shfl_up_sync(0xffu, w, o);
            if (lane >= o) w += x;
        }
        wsum[lane] = w;
    }
    __syncthreads();
    int run = g_blockoff[blockIdx.x] + ((wid > 0) ? wsum[wid - 1] : 0) + (t - s);
#pragma unroll
    for (int j = 0; j < 4; j++) {
        int i = base + tid * 4 + j;
        if (i < NN) { g_rowptr[i] = run; g_cursor[i] = run; }
        run += v[j];
    }
}

__global__ void k_scatter(const int* __restrict__ hl, const int* __restrict__ tl, int E) {
    int e = blockIdx.x * blockDim.x + threadIdx.x;
    if (e >= E) return;
    int h = hl[e], t = tl[e];
    int idx = atomicAdd(&g_cursor[h], 1);
    g_csr_t[idx] = t;
    g_csr_g[idx] = g_dinv[h] * g_dinv[t];
}

__global__ void k_init(const float* __restrict__ ue, const float* __restrict__ ie) {
    int i = blockIdx.x * blockDim.x + threadIdx.x;
    if (i >= NN * (DD / 2)) return;
    int n = i >> 5, h = i & 31;
    const float* src = (n < N_USERS) ? (ue + (size_t)n * DD) : (ie + (size_t)(n - N_USERS) * DD);
    float2 v = make_float2(src[h * 2], src[h * 2 + 1]);
    ((float2*)g_cur)[i] = v;
    ((float2*)g_acc)[i] = v;
}

// one warp per node; lane handles 2 dims (float2); 4-edge unroll (R4-proven).
__global__ void k_prop(const float* __restrict__ src, float* __restrict__ dst) {
    int gw = (blockIdx.x * blockDim.x + threadIdx.x) >> 5;
    int lane = threadIdx.x & 31;
    if (gw >= NN) return;
    int s = g_rowptr[gw], e = g_rowptr[gw + 1];
    float a0 = 0.f, a1 = 0.f;
    int k = s;
    int lo = lane * 2;
    for (; k + 3 < e; k += 4) {
        int   t0 = __ldg(&g_csr_t[k]),     t1 = __ldg(&g_csr_t[k + 1]);
        int   t2 = __ldg(&g_csr_t[k + 2]), t3 = __ldg(&g_csr_t[k + 3]);
        float w0 = __ldg(&g_csr_g[k]),     w1 = __ldg(&g_csr_g[k + 1]);
        float w2 = __ldg(&g_csr_g[k + 2]), w3 = __ldg(&g_csr_g[k + 3]);
        float2 v0 = __ldg((const float2*)(src + (size_t)t0 * DD + lo));
        float2 v1 = __ldg((const float2*)(src + (size_t)t1 * DD + lo));
        float2 v2 = __ldg((const float2*)(src + (size_t)t2 * DD + lo));
        float2 v3 = __ldg((const float2*)(src + (size_t)t3 * DD + lo));
        a0 += w0 * v0.x + w1 * v1.x + w2 * v2.x + w3 * v3.x;
        a1 += w0 * v0.y + w1 * v1.y + w2 * v2.y + w3 * v3.y;
    }
    for (; k < e; k++) {
        int t0 = __ldg(&g_csr_t[k]); float w0 = __ldg(&g_csr_g[k]);
        float2 v0 = __ldg((const float2*)(src + (size_t)t0 * DD + lo));
        a0 += w0 * v0.x;
        a1 += w0 * v0.y;
    }
    size_t o = (size_t)gw * DD + lo;
    ((float2*)(dst + o))[0] = make_float2(a0, a1);
    float2* ap = (float2*)(g_acc + o);
    float2 av = *ap;
    av.x += a0; av.y += a1;
    *ap = av;
}

// KL term over all N rows. block = 256 = 4 rows x 64 dims.
__global__ void k_kl(const float* __restrict__ lw, const float* __restrict__ lb) {
    __shared__ float swT[TS * DD];   // transposed lin_w: swT[t*64+d]
    __shared__ float sb[DD];
    __shared__ float ss[4][TS];
    int tid = threadIdx.x;
    for (int i = tid; i < TS * DD; i += 256) {
        int d = i >> 5, t = i & 31;
        swT[t * DD + d] = lw[i];
    }
    if (tid < DD) sb[tid] = lb[tid];
    __syncthreads();
    int r = tid >> 6;
    int d = tid & 63;
    int row = blockIdx.x * 4 + r;
    if (row < NN && d < TS) ss[r][d] = softplusf(g_acc[(size_t)row * DD + d]);
    __syncthreads();
    float klv = 0.f;
    if (row < NN) {
        float stdv = sb[d] + 1e-8f;
#pragma unroll
        for (int t = 0; t < TS; t++) stdv += ss[r][t] * swT[t * DD + d];
        float mn = g_acc[(size_t)row * DD + d];
        float kl = -0.5f * (1.f + 2.f * stdv - mn * mn - expf(2.f * stdv));
        if (isfinite(kl)) klv = kl;
    }
    float tot = blkSum256(klv);
    if (tid == 0) atomicAdd(&g_sums[1], tot);
}

// BPR + embedding-reg over B samples; one warp per sample.
__global__ void k_bpr(const float* __restrict__ ue, const float* __restrict__ ie,
                      const int* __restrict__ users, const int* __restrict__ pos,
                      const int* __restrict__ neg) {
    int w = (blockIdx.x * blockDim.x + threadIdx.x) >> 5;
    int lane = threadIdx.x & 31;
    if (w >= BB) return;
    int u = users[w], p = pos[w], n = neg[w];
    const float* au = g_acc + (size_t)u * DD;
    const float* ap = g_acc + (size_t)(N_USERS + p) * DD;
    const float* an = g_acc + (size_t)(N_USERS + n) * DD;
    float ps = 0.f, ns = 0.f, es = 0.f;
#pragma unroll
    for (int j = 0; j < 2; j++) {
        int d = lane + 32 * j;
        float x = au[d];
        ps += x * ap[d];
        ns += x * an[d];
        float a = ue[(size_t)u * DD + d], b = ie[(size_t)p * DD + d], c = ie[(size_t)n * DD + d];
        es += a * a + b * b + c * c;
    }
#pragma unroll
    for (int o = 16; o; o >>= 1) {
        ps += __shfl_down_sync(0xffffffffu, ps, o);
        ns += __shfl_down_sync(0xffffffffu, ns, o);
        es += __shfl_down_sync(0xffffffffu, es, o);
    }
    if (lane == 0) {
        atomicAdd(&g_sums[0], softplusf(ns - ps));
        atomicAdd(&g_sums[2], es);
    }
}

// intent regularizer
__global__ void k_intreg(const float* __restrict__ ui, const float* __restrict__ ii) {
    int i = blockIdx.x * blockDim.x + threadIdx.x;
    float v = 0.f;
    if (i < DD * NI)            { float a = ui[i];           v = a * a; }
    else if (i < 2 * DD * NI)   { float a = ii[i - DD * NI]; v = a * a; }
    float tot = blkSum256(v);
    if (threadIdx.x == 0) atomicAdd(&g_sums[3], tot);
}

// per-sample features: normalized gen_emb and intent-projection rows.
__global__ void k_sample(const float* __restrict__ lw, const float* __restrict__ lb,
                         const float* __restrict__ eps,
                         const float* __restrict__ uintm, const float* __restrict__ iintm,
                         const int* __restrict__ users, const int* __restrict__ pos) {
    __shared__ float mrow[DD];
    __shared__ float sp[TS];
    __shared__ float prob[NI];
    __shared__ float partial[4];
    int b = blockIdx.x & (BB - 1);
    int side = blockIdx.x >> 12;
    int tid = threadIdx.x;
    int node = side ? (N_USERS + pos[b]) : users[b];
    const float* intent = side ? iintm : uintm;
    float* outgen = side ? g_igen : g_ugen;
    float* outint = side ? g_iintn : g_uintn;

    if (tid < DD) mrow[tid] = g_acc[(size_t)node * DD + tid];
    __syncthreads();
    if (tid < TS) sp[tid] = softplusf(mrow[tid]);
    __syncthreads();

    float genv = 0.f;
    if (tid < DD) {
        float stdv = lb[tid] + 1e-8f;
#pragma unroll
        for (int t = 0; t < TS; t++) stdv += sp[t] * lw[tid * TS + t];
        genv = mrow[tid] + eps[(size_t)node * DD + tid] * stdv;
    }
    float gn2 = blkSum128(genv * genv, partial);
    if (tid < DD) outgen[b * DD + tid] = genv * rsqrtf(gn2);

    float lg = 0.f;
#pragma unroll
    for (int d = 0; d < DD; d++) lg += mrow[d] * intent[d * NI + tid];
    float mx = blkMax128(lg, partial);
    float ev = expf(lg - mx);
    float ssum = blkSum128(ev, partial);
    prob[tid] = ev;
    __syncthreads();

    float o = 0.f;
    if (tid < DD) {
        const float4* ip = (const float4*)(intent + tid * NI);
        const float4* pp = (const float4*)prob;
#pragma unroll
        for (int k = 0; k < NI / 4; k++) {
            float4 a = ip[k], pq = pp[k];
            o += a.x * pq.x + a.y * pq.y + a.z * pq.z + a.w * pq.w;
        }
        o /= ssum;
    }
    float on2 = blkSum128(o * o, partial);
    if (tid < DD) outint[b * DD + tid] = o * rsqrtf(on2);
}

// InfoNCE partial sums (R4-proven scalar version): grid (BB/256, NSPLIT).
__global__ void k_nce(const float* __restrict__ e1, const float* __restrict__ e2,
                      float* __restrict__ negbuf, float* __restrict__ posbuf) {
    __shared__ float tile[32][DD];
    int tid = threadIdx.x;
    int i = blockIdx.x * 256 + tid;
    float r[DD];
#pragma unroll
    for (int d = 0; d < DD; d++) r[d] = e1[i * DD + d];
    float negs = 0.f, pos = 0.f;
    int j0 = blockIdx.y * JCH;
    for (int jt = 0; jt < JCH; jt += 32) {
#pragma unroll
        for (int q = 0; q < 8; q++) {
            int idx = tid + q * 256;
            tile[idx >> 6][idx & 63] = e2[(size_t)(j0 + jt) * DD + idx];
        }
        __syncthreads();
#pragma unroll 4
        for (int jj = 0; jj < 32; jj++) {
            float dot = 0.f;
#pragma unroll
            for (int d = 0; d < DD; d++) dot += r[d] * tile[jj][d];
            float evv = __expf(dot * (1.f / TEMP));
            negs += evv;
            if (j0 + jt + jj == i) pos = evv;
        }
        __syncthreads();
    }
    atomicAdd(&negbuf[i], negs);
    if (i >= j0 && i < j0 + JCH) posbuf[i] = pos;
}

// fused nce-final + output (single block of 256)
__global__ void k_final(float* __restrict__ out) {
    int tid = threadIdx.x;
    float cl = 0.f;
    for (int i = tid; i < 2 * BB; i += 256)
        cl += -logf(g_pos[i] / (g_neg[i] + 1e-8f) + 1e-8f);
    float cltot = blkSum256(cl);
    if (tid == 0) {
        float bpr = g_sums[0] / (float)BB;
        float kl  = KL_REG * (g_sums[1] / (float)NN);
        out[0] = bpr + kl;
        out[1] = SSL_REG * (cltot / (float)BB);
        out[2] = EMB_REG * g_sums[2];
        out[3] = INT_REG * g_sums[3];
    }
}

// ---------------- launch ------------------------------------------------------
extern "C" void kernel_launch(void* const* d_in, const int* in_sizes, int n_in,
                              void* d_out, int out_size) {
    const float* user_emb = (const float*)d_in[0];
    const float* item_emb = (const float*)d_in[1];
    const float* uintm    = (const float*)d_in[2];
    const float* iintm    = (const float*)d_in[3];
    const float* lw       = (const float*)d_in[4];
    const float* lb       = (const float*)d_in[5];
    const float* eps      = (const float*)d_in[6];
    const int*   hl       = (const int*)d_in[7];
    const int*   tl       = (const int*)d_in[8];
    const int*   users    = (const int*)d_in[9];
    const int*   pos      = (const int*)d_in[10];
    const int*   neg      = (const int*)d_in[11];
    int E = in_sizes[7];
    float* out = (float*)d_out;

    void *p_cur, *p_nxt, *p_ugen, *p_uint, *p_igen, *p_iint, *p_neg, *p_pos;
    cudaGetSymbolAddress(&p_cur, g_cur);
    cudaGetSymbolAddress(&p_nxt, g_nxt);
    cudaGetSymbolAddress(&p_ugen, g_ugen);
    cudaGetSymbolAddress(&p_uint, g_uintn);
    cudaGetSymbolAddress(&p_igen, g_igen);
    cudaGetSymbolAddress(&p_iint, g_iintn);
    cudaGetSymbolAddress(&p_neg,  g_neg);
    cudaGetSymbolAddress(&p_pos,  g_pos);

    k_clear<<<(NN + 255) / 256, 256>>>();
    k_deg<<<(E + 255) / 256, 256>>>(hl, E);
    k_scanA<<<NBLK_SCAN, 256>>>();
    k_scanB<<<1, 32>>>();
    k_scanC<<<NBLK_SCAN, 256>>>();
    k_scatter<<<(E + 255) / 256, 256>>>(hl, tl, E);
    k_init<<<(NN * (DD / 2) + 255) / 256, 256>>>(user_emb, item_emb);

    k_prop<<<(NN * 32 + 255) / 256, 256>>>((const float*)p_cur, (float*)p_nxt);
    k_prop<<<(NN * 32 + 255) / 256, 256>>>((const float*)p_nxt, (float*)p_cur);
    k_prop<<<(NN * 32 + 255) / 256, 256>>>((const float*)p_cur, (float*)p_nxt);

    k_kl<<<(NN + 3) / 4, 256>>>(lw, lb);
    k_bpr<<<(BB * 32 + 255) / 256, 256>>>(user_emb, item_emb, users, pos, neg);
    k_intreg<<<(2 * DD * NI + 255) / 256, 256>>>(uintm, iintm);
    k_sample<<<2 * BB, 128>>>(lw, lb, eps, uintm, iintm, users, pos);

    {
        dim3 grid(BB / 256, NSPLIT);
        k_nce<<<grid, 256>>>((const float*)p_ugen, (const float*)p_uint,
                             (float*)p_neg, (float*)p_pos);
        k_nce<<<grid, 256>>>((const float*)p_igen, (const float*)p_iint,
                             (float*)p_neg + BB, (float*)p_pos + BB);
    }
    k_final<<<1, 256>>>(out);
}

// round 11
// speedup vs baseline: 1.5891x; 1.0128x over previous
#include <cuda_runtime.h>
#include <math.h>

#define N_USERS 50000
#define N_ITEMS 100000
#define NN      150000
#define DD      64
#define NI      128
#define TS      32
#define TEMP    0.2f
#define KL_REG  0.01f
#define EMB_REG 1e-5f
#define INT_REG 1e-5f
#define SSL_REG 0.1f
#define BB      4096
#define E_TOT   3150000
#define NSPLIT  16
#define JCH     (BB / NSPLIT)

#define SCAN_CHUNK 1024
#define NBLK_SCAN  ((NN + SCAN_CHUNK - 1) / SCAN_CHUNK)   // 147

// ---------------- scratch (device globals; no allocation allowed) ------------
__device__ int   g_deg[NN];
__device__ float g_dinv[NN];
__device__ int   g_rowptr[NN + 1];
__device__ int   g_cursor[NN];
__device__ int   g_blocksum[NBLK_SCAN];
__device__ int   g_blockoff[NBLK_SCAN];
__device__ int   g_csr_t[E_TOT];
__device__ float g_csr_g[E_TOT];
__device__ __align__(16) unsigned g_curb[(size_t)NN * (DD / 2)];  // bf16x2 packed
__device__ __align__(16) unsigned g_nxtb[(size_t)NN * (DD / 2)];  // bf16x2 packed
__device__ __align__(16) float g_acc[(size_t)NN * DD];
__device__ __align__(16) float g_ugen[BB * DD];
__device__ __align__(16) float g_uintn[BB * DD];
__device__ __align__(16) float g_igen[BB * DD];
__device__ __align__(16) float g_iintn[BB * DD];
__device__ float g_neg[2 * BB];
__device__ float g_pos[2 * BB];
__device__ float g_sums[8];   // 0:bpr 1:kl 2:emb 3:int 4:cl

// ---------------- helpers ----------------------------------------------------
__device__ __forceinline__ float softplusf(float x) {
    return x > 0.f ? x + log1pf(expf(-x)) : log1pf(expf(x));
}

// exact bf16x2 -> float2 unpack: pure ALU (shift/and), no CVT
__device__ __forceinline__ float2 bf2f(unsigned x) {
    float2 r;
    r.x = __uint_as_float(x << 16);
    r.y = __uint_as_float(x & 0xffff0000u);
    return r;
}

// float2 -> bf16x2 pack (RN), one CVT
__device__ __forceinline__ unsigned f2bf(float lo, float hi) {
    unsigned r;
    asm("cvt.rn.bf16x2.f32 %0, %1, %2;" : "=r"(r) : "f"(hi), "f"(lo));
    return r;
}

__device__ __forceinline__ float blkSum256(float v) {
    __shared__ float sp[8];
    int lane = threadIdx.x & 31, wid = threadIdx.x >> 5;
#pragma unroll
    for (int o = 16; o; o >>= 1) v += __shfl_down_sync(0xffffffffu, v, o);
    if (lane == 0) sp[wid] = v;
    __syncthreads();
    v = (threadIdx.x < 8) ? sp[threadIdx.x] : 0.f;
    if (wid == 0) {
#pragma unroll
        for (int o = 4; o; o >>= 1) v += __shfl_down_sync(0xffffffffu, v, o);
    }
    __syncthreads();
    return v;
}

__device__ __forceinline__ int blkSum256i(int v) {
    __shared__ int sp[8];
    int lane = threadIdx.x & 31, wid = threadIdx.x >> 5;
#pragma unroll
    for (int o = 16; o; o >>= 1) v += __shfl_down_sync(0xffffffffu, v, o);
    if (lane == 0) sp[wid] = v;
    __syncthreads();
    v = (threadIdx.x < 8) ? sp[threadIdx.x] : 0;
    if (wid == 0) {
#pragma unroll
        for (int o = 4; o; o >>= 1) v += __shfl_down_sync(0xffffffffu, v, o);
    }
    __syncthreads();
    return v;
}

__device__ __forceinline__ float blkSum128(float v, float* partial) {
    int lane = threadIdx.x & 31, wid = threadIdx.x >> 5;
#pragma unroll
    for (int o = 16; o; o >>= 1) v += __shfl_down_sync(0xffffffffu, v, o);
    if (lane == 0) partial[wid] = v;
    __syncthreads();
    float s = partial[0] + partial[1] + partial[2] + partial[3];
    __syncthreads();
    return s;
}

__device__ __forceinline__ float blkMax128(float v, float* partial) {
    int lane = threadIdx.x & 31, wid = threadIdx.x >> 5;
#pragma unroll
    for (int o = 16; o; o >>= 1) v = fmaxf(v, __shfl_down_sync(0xffffffffu, v, o));
    if (lane == 0) partial[wid] = v;
    __syncthreads();
    float s = fmaxf(fmaxf(partial[0], partial[1]), fmaxf(partial[2], partial[3]));
    __syncthreads();
    return s;
}

// ---------------- kernels ----------------------------------------------------
__global__ void k_clear() {
    int i = blockIdx.x * blockDim.x + threadIdx.x;
    if (i < NN) g_deg[i] = 0;
    if (i < 8) g_sums[i] = 0.f;
    if (i < 2 * BB) { g_neg[i] = 0.f; g_pos[i] = 0.f; }
}

__global__ void k_deg(const int* __restrict__ hl, int E) {
    int e = blockIdx.x * blockDim.x + threadIdx.x;
    if (e < E) atomicAdd(&g_deg[hl[e]], 1);
}

// chunk reduce + dinv fused. grid NBLK_SCAN, block 256
__global__ void k_scanA() {
    int base = blockIdx.x * SCAN_CHUNK;
    int v = 0;
    for (int i = threadIdx.x; i < SCAN_CHUNK; i += 256) {
        int idx = base + i;
        if (idx < NN) {
            int d = g_deg[idx];
            v += d;
            g_dinv[idx] = rsqrtf((float)d);
        }
    }
    int tot = blkSum256i(v);
    if (threadIdx.x == 0) g_blocksum[blockIdx.x] = tot;
}

// single-warp shuffle scan of 147 partials (5 values/lane)
__global__ void k_scanB() {
    int lane = threadIdx.x;
    int v[5]; int s = 0;
#pragma unroll
    for (int j = 0; j < 5; j++) {
        int i = lane * 5 + j;
        v[j] = (i < NBLK_SCAN) ? g_blocksum[i] : 0;
        s += v[j];
    }
    int t = s;
#pragma unroll
    for (int o = 1; o < 32; o <<= 1) {
        int x = __shfl_up_sync(0xffffffffu, t, o);
        if (lane >= o) t += x;
    }
    int run = t - s;
#pragma unroll
    for (int j = 0; j < 5; j++) {
        int i = lane * 5 + j;
        if (i < NBLK_SCAN) g_blockoff[i] = run;
        run += v[j];
    }
    if (lane == 31) g_rowptr[NN] = t;
}

// grid NBLK_SCAN, block 256, 4 elems/thread (256*4 = 1024 = SCAN_CHUNK)
__global__ void k_scanC() {
    __shared__ int wsum[8];
    int base = blockIdx.x * SCAN_CHUNK;
    int tid = threadIdx.x, lane = tid & 31, wid = tid >> 5;
    int v[4]; int s = 0;
#pragma unroll
    for (int j = 0; j < 4; j++) {
        int i = base + tid * 4 + j;
        v[j] = (i < NN) ? g_deg[i] : 0;
        s += v[j];
    }
    int t = s;
#pragma unroll
    for (int o = 1; o < 32; o <<= 1) {
        int x = __shfl_up_sync(0xffffffffu, t, o);
        if (lane >= o) t += x;
    }
    if (lane == 31) wsum[wid] = t;
    __syncthreads();
    if (wid == 0 && lane < 8) {
        int w = wsum[lane];
#pragma unroll
        for (int o = 1; o < 8; o <<= 1) {
            int x = __shfl_up_sync(0xffu, w, o);
            if (lane >= o) w += x;
        }
        wsum[lane] = w;
    }
    __syncthreads();
    int run = g_blockoff[blockIdx.x] + ((wid > 0) ? wsum[wid - 1] : 0) + (t - s);
#pragma unroll
    for (int j = 0; j < 4; j++) {
        int i = base + tid * 4 + j;
        if (i < NN) { g_rowptr[i] = run; g_cursor[i] = run; }
        run += v[j];
    }
}

__global__ void k_scatter(const int* __restrict__ hl, const int* __restrict__ tl, int E) {
    int e = blockIdx.x * blockDim.x + threadIdx.x;
    if (e >= E) return;
    int h = hl[e], t = tl[e];
    int idx = atomicAdd(&g_cursor[h], 1);
    g_csr_t[idx] = t;
    g_csr_g[idx] = g_dinv[h] * g_dinv[t];
}

__global__ void k_init(const float* __restrict__ ue, const float* __restrict__ ie) {
    int i = blockIdx.x * blockDim.x + threadIdx.x;
    if (i >= NN * (DD / 2)) return;
    int n = i >> 5, h = i & 31;
    const float* src = (n < N_USERS) ? (ue + (size_t)n * DD) : (ie + (size_t)(n - N_USERS) * DD);
    float2 v = make_float2(src[h * 2], src[h * 2 + 1]);
    g_curb[i] = f2bf(v.x, v.y);
    ((float2*)g_acc)[i] = v;
}

// one warp per node; lane handles 2 dims (one bf16x2); 4-edge unroll.
// Unpack is shift/and on ALU pipe — no CVT in hot loop. Accumulate fp32.
__global__ void k_prop(const unsigned* __restrict__ src, unsigned* __restrict__ dst) {
    int gw = (blockIdx.x * blockDim.x + threadIdx.x) >> 5;
    int lane = threadIdx.x & 31;
    if (gw >= NN) return;
    int s = g_rowptr[gw], e = g_rowptr[gw + 1];
    float a0 = 0.f, a1 = 0.f;
    int k = s;
    for (; k + 3 < e; k += 4) {
        int   t0 = __ldg(&g_csr_t[k]),     t1 = __ldg(&g_csr_t[k + 1]);
        int   t2 = __ldg(&g_csr_t[k + 2]), t3 = __ldg(&g_csr_t[k + 3]);
        float w0 = __ldg(&g_csr_g[k]),     w1 = __ldg(&g_csr_g[k + 1]);
        float w2 = __ldg(&g_csr_g[k + 2]), w3 = __ldg(&g_csr_g[k + 3]);
        unsigned b0 = __ldg(&src[(size_t)t0 * 32 + lane]);
        unsigned b1 = __ldg(&src[(size_t)t1 * 32 + lane]);
        unsigned b2 = __ldg(&src[(size_t)t2 * 32 + lane]);
        unsigned b3 = __ldg(&src[(size_t)t3 * 32 + lane]);
        float2 v0 = bf2f(b0), v1 = bf2f(b1), v2 = bf2f(b2), v3 = bf2f(b3);
        a0 += w0 * v0.x + w1 * v1.x + w2 * v2.x + w3 * v3.x;
        a1 += w0 * v0.y + w1 * v1.y + w2 * v2.y + w3 * v3.y;
    }
    for (; k < e; k++) {
        int t0 = __ldg(&g_csr_t[k]); float w0 = __ldg(&g_csr_g[k]);
        float2 v0 = bf2f(__ldg(&src[(size_t)t0 * 32 + lane]));
        a0 += w0 * v0.x;
        a1 += w0 * v0.y;
    }
    dst[(size_t)gw * 32 + lane] = f2bf(a0, a1);
    float2* ap = (float2*)g_acc + (size_t)gw * 32 + lane;
    float2 av = *ap;
    av.x += a0; av.y += a1;
    *ap = av;
}

// KL term over all N rows. block = 256 = 4 rows x 64 dims.
__global__ void k_kl(const float* __restrict__ lw, const float* __restrict__ lb) {
    __shared__ float swT[TS * DD];   // transposed lin_w: swT[t*64+d]
    __shared__ float sb[DD];
    __shared__ float ss[4][TS];
    int tid = threadIdx.x;
    for (int i = tid; i < TS * DD; i += 256) {
        int d = i >> 5, t = i & 31;
        swT[t * DD + d] = lw[i];
    }
    if (tid < DD) sb[tid] = lb[tid];
    __syncthreads();
    int r = tid >> 6;
    int d = tid & 63;
    int row = blockIdx.x * 4 + r;
    if (row < NN && d < TS) ss[r][d] = softplusf(g_acc[(size_t)row * DD + d]);
    __syncthreads();
    float klv = 0.f;
    if (row < NN) {
        float stdv = sb[d] + 1e-8f;
#pragma unroll
        for (int t = 0; t < TS; t++) stdv += ss[r][t] * swT[t * DD + d];
        float mn = g_acc[(size_t)row * DD + d];
        float kl = -0.5f * (1.f + 2.f * stdv - mn * mn - expf(2.f * stdv));
        if (isfinite(kl)) klv = kl;
    }
    float tot = blkSum256(klv);
    if (tid == 0) atomicAdd(&g_sums[1], tot);
}

// BPR + embedding-reg over B samples; one warp per sample.
__global__ void k_bpr(const float* __restrict__ ue, const float* __restrict__ ie,
                      const int* __restrict__ users, const int* __restrict__ pos,
                      const int* __restrict__ neg) {
    int w = (blockIdx.x * blockDim.x + threadIdx.x) >> 5;
    int lane = threadIdx.x & 31;
    if (w >= BB) return;
    int u = users[w], p = pos[w], n = neg[w];
    const float* au = g_acc + (size_t)u * DD;
    const float* ap = g_acc + (size_t)(N_USERS + p) * DD;
    const float* an = g_acc + (size_t)(N_USERS + n) * DD;
    float ps = 0.f, ns = 0.f, es = 0.f;
#pragma unroll
    for (int j = 0; j < 2; j++) {
        int d = lane + 32 * j;
        float x = au[d];
        ps += x * ap[d];
        ns += x * an[d];
        float a = ue[(size_t)u * DD + d], b = ie[(size_t)p * DD + d], c = ie[(size_t)n * DD + d];
        es += a * a + b * b + c * c;
    }
#pragma unroll
    for (int o = 16; o; o >>= 1) {
        ps += __shfl_down_sync(0xffffffffu, ps, o);
        ns += __shfl_down_sync(0xffffffffu, ns, o);
        es += __shfl_down_sync(0xffffffffu, es, o);
    }
    if (lane == 0) {
        atomicAdd(&g_sums[0], softplusf(ns - ps));
        atomicAdd(&g_sums[2], es);
    }
}

// intent regularizer
__global__ void k_intreg(const float* __restrict__ ui, const float* __restrict__ ii) {
    int i = blockIdx.x * blockDim.x + threadIdx.x;
    float v = 0.f;
    if (i < DD * NI)            { float a = ui[i];           v = a * a; }
    else if (i < 2 * DD * NI)   { float a = ii[i - DD * NI]; v = a * a; }
    float tot = blkSum256(v);
    if (threadIdx.x == 0) atomicAdd(&g_sums[3], tot);
}

// per-sample features: normalized gen_emb and intent-projection rows.
__global__ void k_sample(const float* __restrict__ lw, const float* __restrict__ lb,
                         const float* __restrict__ eps,
                         const float* __restrict__ uintm, const float* __restrict__ iintm,
                         const int* __restrict__ users, const int* __restrict__ pos) {
    __shared__ float mrow[DD];
    __shared__ float sp[TS];
    __shared__ float prob[NI];
    __shared__ float partial[4];
    int b = blockIdx.x & (BB - 1);
    int side = blockIdx.x >> 12;
    int tid = threadIdx.x;
    int node = side ? (N_USERS + pos[b]) : users[b];
    const float* intent = side ? iintm : uintm;
    float* outgen = side ? g_igen : g_ugen;
    float* outint = side ? g_iintn : g_uintn;

    if (tid < DD) mrow[tid] = g_acc[(size_t)node * DD + tid];
    __syncthreads();
    if (tid < TS) sp[tid] = softplusf(mrow[tid]);
    __syncthreads();

    float genv = 0.f;
    if (tid < DD) {
        float stdv = lb[tid] + 1e-8f;
#pragma unroll
        for (int t = 0; t < TS; t++) stdv += sp[t] * lw[tid * TS + t];
        genv = mrow[tid] + eps[(size_t)node * DD + tid] * stdv;
    }
    float gn2 = blkSum128(genv * genv, partial);
    if (tid < DD) outgen[b * DD + tid] = genv * rsqrtf(gn2);

    float lg = 0.f;
#pragma unroll
    for (int d = 0; d < DD; d++) lg += mrow[d] * intent[d * NI + tid];
    float mx = blkMax128(lg, partial);
    float ev = expf(lg - mx);
    float ssum = blkSum128(ev, partial);
    prob[tid] = ev;
    __syncthreads();

    float o = 0.f;
    if (tid < DD) {
        const float4* ip = (const float4*)(intent + tid * NI);
        const float4* pp = (const float4*)prob;
#pragma unroll
        for (int k = 0; k < NI / 4; k++) {
            float4 a = ip[k], pq = pp[k];
            o += a.x * pq.x + a.y * pq.y + a.z * pq.z + a.w * pq.w;
        }
        o /= ssum;
    }
    float on2 = blkSum128(o * o, partial);
    if (tid < DD) outint[b * DD + tid] = o * rsqrtf(on2);
}

// InfoNCE partial sums (R4-proven scalar version): grid (BB/256, NSPLIT).
__global__ void k_nce(const float* __restrict__ e1, const float* __restrict__ e2,
                      float* __restrict__ negbuf, float* __restrict__ posbuf) {
    __shared__ float tile[32][DD];
    int tid = threadIdx.x;
    int i = blockIdx.x * 256 + tid;
    float r[DD];
#pragma unroll
    for (int d = 0; d < DD; d++) r[d] = e1[i * DD + d];
    float negs = 0.f, pos = 0.f;
    int j0 = blockIdx.y * JCH;
    for (int jt = 0; jt < JCH; jt += 32) {
#pragma unroll
        for (int q = 0; q < 8; q++) {
            int idx = tid + q * 256;
            tile[idx >> 6][idx & 63] = e2[(size_t)(j0 + jt) * DD + idx];
        }
        __syncthreads();
#pragma unroll 4
        for (int jj = 0; jj < 32; jj++) {
            float dot = 0.f;
#pragma unroll
            for (int d = 0; d < DD; d++) dot += r[d] * tile[jj][d];
            float evv = __expf(dot * (1.f / TEMP));
            negs += evv;
            if (j0 + jt + jj == i) pos = evv;
        }
        __syncthreads();
    }
    atomicAdd(&negbuf[i], negs);
    if (i >= j0 && i < j0 + JCH) posbuf[i] = pos;
}

// fused nce-final + output (single block of 256)
__global__ void k_final(float* __restrict__ out) {
    int tid = threadIdx.x;
    float cl = 0.f;
    for (int i = tid; i < 2 * BB; i += 256)
        cl += -logf(g_pos[i] / (g_neg[i] + 1e-8f) + 1e-8f);
    float cltot = blkSum256(cl);
    if (tid == 0) {
        float bpr = g_sums[0] / (float)BB;
        float kl  = KL_REG * (g_sums[1] / (float)NN);
        out[0] = bpr + kl;
        out[1] = SSL_REG * (cltot / (float)BB);
        out[2] = EMB_REG * g_sums[2];
        out[3] = INT_REG * g_sums[3];
    }
}

// ---------------- launch ------------------------------------------------------
extern "C" void kernel_launch(void* const* d_in, const int* in_sizes, int n_in,
                              void* d_out, int out_size) {
    const float* user_emb = (const float*)d_in[0];
    const float* item_emb = (const float*)d_in[1];
    const float* uintm    = (const float*)d_in[2];
    const float* iintm    = (const float*)d_in[3];
    const float* lw       = (const float*)d_in[4];
    const float* lb       = (const float*)d_in[5];
    const float* eps      = (const float*)d_in[6];
    const int*   hl       = (const int*)d_in[7];
    const int*   tl       = (const int*)d_in[8];
    const int*   users    = (const int*)d_in[9];
    const int*   pos      = (const int*)d_in[10];
    const int*   neg      = (const int*)d_in[11];
    int E = in_sizes[7];
    float* out = (float*)d_out;

    void *p_cur, *p_nxt, *p_ugen, *p_uint, *p_igen, *p_iint, *p_neg, *p_pos;
    cudaGetSymbolAddress(&p_cur, g_curb);
    cudaGetSymbolAddress(&p_nxt, g_nxtb);
    cudaGetSymbolAddress(&p_ugen, g_ugen);
    cudaGetSymbolAddress(&p_uint, g_uintn);
    cudaGetSymbolAddress(&p_igen, g_igen);
    cudaGetSymbolAddress(&p_iint, g_iintn);
    cudaGetSymbolAddress(&p_neg,  g_neg);
    cudaGetSymbolAddress(&p_pos,  g_pos);

    k_clear<<<(NN + 255) / 256, 256>>>();
    k_deg<<<(E + 255) / 256, 256>>>(hl, E);
    k_scanA<<<NBLK_SCAN, 256>>>();
    k_scanB<<<1, 32>>>();
    k_scanC<<<NBLK_SCAN, 256>>>();
    k_scatter<<<(E + 255) / 256, 256>>>(hl, tl, E);
    k_init<<<(NN * (DD / 2) + 255) / 256, 256>>>(user_emb, item_emb);

    k_prop<<<(NN * 32 + 255) / 256, 256>>>((const unsigned*)p_cur, (unsigned*)p_nxt);
    k_prop<<<(NN * 32 + 255) / 256, 256>>>((const unsigned*)p_nxt, (unsigned*)p_cur);
    k_prop<<<(NN * 32 + 255) / 256, 256>>>((const unsigned*)p_cur, (unsigned*)p_nxt);

    k_kl<<<(NN + 3) / 4, 256>>>(lw, lb);
    k_bpr<<<(BB * 32 + 255) / 256, 256>>>(user_emb, item_emb, users, pos, neg);
    k_intreg<<<(2 * DD * NI + 255) / 256, 256>>>(uintm, iintm);
    k_sample<<<2 * BB, 128>>>(lw, lb, eps, uintm, iintm, users, pos);

    {
        dim3 grid(BB / 256, NSPLIT);
        k_nce<<<grid, 256>>>((const float*)p_ugen, (const float*)p_uint,
                             (float*)p_neg, (float*)p_pos);
        k_nce<<<grid, 256>>>((const float*)p_igen, (const float*)p_iint,
                             (float*)p_neg + BB, (float*)p_pos + BB);
    }
    k_final<<<1, 256>>>(out);
}

// round 13
// speedup vs baseline: 1.8867x; 1.1873x over previous
#include <cuda_runtime.h>
#include <cuda_fp16.h>
#include <math.h>

#define N_USERS 50000
#define N_ITEMS 100000
#define NN      150000
#define DD      64
#define NI      128
#define TS      32
#define TEMP    0.2f
#define KL_REG  0.01f
#define EMB_REG 1e-5f
#define INT_REG 1e-5f
#define SSL_REG 0.1f
#define BB      4096
#define E_TOT   3150000

#define SCAN_CHUNK 1024
#define NBLK_SCAN  ((NN + SCAN_CHUNK - 1) / SCAN_CHUNK)   // 147

#define XS 72   // padded smem row stride (halves) for mma tiles

// ---------------- scratch (device globals; no allocation allowed) ------------
__device__ int   g_deg[NN];
__device__ float g_dinv[NN];
__device__ int   g_rowptr[NN + 1];
__device__ int   g_cursor[NN];
__device__ int   g_blocksum[NBLK_SCAN];
__device__ int   g_blockoff[NBLK_SCAN];
__device__ int   g_csr_t[E_TOT];
__device__ float g_csr_g[E_TOT];
__device__ __align__(16) unsigned g_curb[(size_t)NN * (DD / 2)];  // bf16x2 packed
__device__ __align__(16) unsigned g_nxtb[(size_t)NN * (DD / 2)];  // bf16x2 packed
__device__ __align__(16) float g_acc[(size_t)NN * DD];
__device__ __align__(16) __half g_ugenh[BB * DD];
__device__ __align__(16) __half g_uinth[BB * DD];
__device__ __align__(16) __half g_igenh[BB * DD];
__device__ __align__(16) __half g_iinth[BB * DD];
__device__ float g_neg[2 * BB];
__device__ float g_pos[2 * BB];
__device__ float g_sums[8];   // 0:bpr 1:kl 2:emb 3:int 4:cl

// ---------------- helpers ----------------------------------------------------
__device__ __forceinline__ float softplusf(float x) {
    return x > 0.f ? x + log1pf(expf(-x)) : log1pf(expf(x));
}

__device__ __forceinline__ float2 bf2f(unsigned x) {
    float2 r;
    r.x = __uint_as_float(x << 16);
    r.y = __uint_as_float(x & 0xffff0000u);
    return r;
}

__device__ __forceinline__ unsigned f2bf(float lo, float hi) {
    unsigned r;
    asm("cvt.rn.bf16x2.f32 %0, %1, %2;" : "=r"(r) : "f"(hi), "f"(lo));
    return r;
}

__device__ __forceinline__ float blkSum256(float v) {
    __shared__ float sp[8];
    int lane = threadIdx.x & 31, wid = threadIdx.x >> 5;
#pragma unroll
    for (int o = 16; o; o >>= 1) v += __shfl_down_sync(0xffffffffu, v, o);
    if (lane == 0) sp[wid] = v;
    __syncthreads();
    v = (threadIdx.x < 8) ? sp[threadIdx.x] : 0.f;
    if (wid == 0) {
#pragma unroll
        for (int o = 4; o; o >>= 1) v += __shfl_down_sync(0xffffffffu, v, o);
    }
    __syncthreads();
    return v;
}

__device__ __forceinline__ int blkSum256i(int v) {
    __shared__ int sp[8];
    int lane = threadIdx.x & 31, wid = threadIdx.x >> 5;
#pragma unroll
    for (int o = 16; o; o >>= 1) v += __shfl_down_sync(0xffffffffu, v, o);
    if (lane == 0) sp[wid] = v;
    __syncthreads();
    v = (threadIdx.x < 8) ? sp[threadIdx.x] : 0;
    if (wid == 0) {
#pragma unroll
        for (int o = 4; o; o >>= 1) v += __shfl_down_sync(0xffffffffu, v, o);
    }
    __syncthreads();
    return v;
}

__device__ __forceinline__ float blkSum128(float v, float* partial) {
    int lane = threadIdx.x & 31, wid = threadIdx.x >> 5;
#pragma unroll
    for (int o = 16; o; o >>= 1) v += __shfl_down_sync(0xffffffffu, v, o);
    if (lane == 0) partial[wid] = v;
    __syncthreads();
    float s = partial[0] + partial[1] + partial[2] + partial[3];
    __syncthreads();
    return s;
}

__device__ __forceinline__ float blkMax128(float v, float* partial) {
    int lane = threadIdx.x & 31, wid = threadIdx.x >> 5;
#pragma unroll
    for (int o = 16; o; o >>= 1) v = fmaxf(v, __shfl_down_sync(0xffffffffu, v, o));
    if (lane == 0) partial[wid] = v;
    __syncthreads();
    float s = fmaxf(fmaxf(partial[0], partial[1]), fmaxf(partial[2], partial[3]));
    __syncthreads();
    return s;
}

// ---------------- kernels ----------------------------------------------------
__global__ void k_clear() {
    int i = blockIdx.x * blockDim.x + threadIdx.x;
    if (i < NN) g_deg[i] = 0;
    if (i < 8) g_sums[i] = 0.f;
    if (i < 2 * BB) { g_neg[i] = 0.f; g_pos[i] = 0.f; }
}

__global__ void k_deg(const int* __restrict__ hl, int E) {
    int e = blockIdx.x * blockDim.x + threadIdx.x;
    if (e < E) atomicAdd(&g_deg[hl[e]], 1);
}

__global__ void k_scanA() {
    int base = blockIdx.x * SCAN_CHUNK;
    int v = 0;
    for (int i = threadIdx.x; i < SCAN_CHUNK; i += 256) {
        int idx = base + i;
        if (idx < NN) {
            int d = g_deg[idx];
            v += d;
            g_dinv[idx] = rsqrtf((float)d);
        }
    }
    int tot = blkSum256i(v);
    if (threadIdx.x == 0) g_blocksum[blockIdx.x] = tot;
}

__global__ void k_scanB() {
    int lane = threadIdx.x;
    int v[5]; int s = 0;
#pragma unroll
    for (int j = 0; j < 5; j++) {
        int i = lane * 5 + j;
        v[j] = (i < NBLK_SCAN) ? g_blocksum[i] : 0;
        s += v[j];
    }
    int t = s;
#pragma unroll
    for (int o = 1; o < 32; o <<= 1) {
        int x = __shfl_up_sync(0xffffffffu, t, o);
        if (lane >= o) t += x;
    }
    int run = t - s;
#pragma unroll
    for (int j = 0; j < 5; j++) {
        int i = lane * 5 + j;
        if (i < NBLK_SCAN) g_blockoff[i] = run;
        run += v[j];
    }
    if (lane == 31) g_rowptr[NN] = t;
}

__global__ void k_scanC() {
    __shared__ int wsum[8];
    int base = blockIdx.x * SCAN_CHUNK;
    int tid = threadIdx.x, lane = tid & 31, wid = tid >> 5;
    int v[4]; int s = 0;
#pragma unroll
    for (int j = 0; j < 4; j++) {
        int i = base + tid * 4 + j;
        v[j] = (i < NN) ? g_deg[i] : 0;
        s += v[j];
    }
    int t = s;
#pragma unroll
    for (int o = 1; o < 32; o <<= 1) {
        int x = __shfl_up_sync(0xffffffffu, t, o);
        if (lane >= o) t += x;
    }
    if (lane == 31) wsum[wid] = t;
    __syncthreads();
    if (wid == 0 && lane < 8) {
        int w = wsum[lane];
#pragma unroll
        for (int o = 1; o < 8; o <<= 1) {
            int x = __shfl_up_sync(0xffu, w, o);
            if (lane >= o) w += x;
        }
        wsum[lane] = w;
    }
    __syncthreads();
    int run = g_blockoff[blockIdx.x] + ((wid > 0) ? wsum[wid - 1] : 0) + (t - s);
#pragma unroll
    for (int j = 0; j < 4; j++) {
        int i = base + tid * 4 + j;
        if (i < NN) { g_rowptr[i] = run; g_cursor[i] = run; }
        run += v[j];
    }
}

__global__ void k_scatter(const int* __restrict__ hl, const int* __restrict__ tl, int E) {
    int e = blockIdx.x * blockDim.x + threadIdx.x;
    if (e >= E) return;
    int h = hl[e], t = tl[e];
    int idx = atomicAdd(&g_cursor[h], 1);
    g_csr_t[idx] = t;
    g_csr_g[idx] = g_dinv[h] * g_dinv[t];
}

__global__ void k_init(const float* __restrict__ ue, const float* __restrict__ ie) {
    int i = blockIdx.x * blockDim.x + threadIdx.x;
    if (i >= NN * (DD / 2)) return;
    int n = i >> 5, h = i & 31;
    const float* src = (n < N_USERS) ? (ue + (size_t)n * DD) : (ie + (size_t)(n - N_USERS) * DD);
    float2 v = make_float2(src[h * 2], src[h * 2 + 1]);
    g_curb[i] = f2bf(v.x, v.y);
    ((float2*)g_acc)[i] = v;
}

// one warp per node; lane handles 2 dims (one bf16x2); 4-edge unroll.
__global__ void k_prop(const unsigned* __restrict__ src, unsigned* __restrict__ dst) {
    int gw = (blockIdx.x * blockDim.x + threadIdx.x) >> 5;
    int lane = threadIdx.x & 31;
    if (gw >= NN) return;
    int s = g_rowptr[gw], e = g_rowptr[gw + 1];
    float a0 = 0.f, a1 = 0.f;
    int k = s;
    for (; k + 3 < e; k += 4) {
        int   t0 = __ldg(&g_csr_t[k]),     t1 = __ldg(&g_csr_t[k + 1]);
        int   t2 = __ldg(&g_csr_t[k + 2]), t3 = __ldg(&g_csr_t[k + 3]);
        float w0 = __ldg(&g_csr_g[k]),     w1 = __ldg(&g_csr_g[k + 1]);
        float w2 = __ldg(&g_csr_g[k + 2]), w3 = __ldg(&g_csr_g[k + 3]);
        unsigned b0 = __ldg(&src[(size_t)t0 * 32 + lane]);
        unsigned b1 = __ldg(&src[(size_t)t1 * 32 + lane]);
        unsigned b2 = __ldg(&src[(size_t)t2 * 32 + lane]);
        unsigned b3 = __ldg(&src[(size_t)t3 * 32 + lane]);
        float2 v0 = bf2f(b0), v1 = bf2f(b1), v2 = bf2f(b2), v3 = bf2f(b3);
        a0 += w0 * v0.x + w1 * v1.x + w2 * v2.x + w3 * v3.x;
        a1 += w0 * v0.y + w1 * v1.y + w2 * v2.y + w3 * v3.y;
    }
    for (; k < e; k++) {
        int t0 = __ldg(&g_csr_t[k]); float w0 = __ldg(&g_csr_g[k]);
        float2 v0 = bf2f(__ldg(&src[(size_t)t0 * 32 + lane]));
        a0 += w0 * v0.x;
        a1 += w0 * v0.y;
    }
    dst[(size_t)gw * 32 + lane] = f2bf(a0, a1);
    float2* ap = (float2*)g_acc + (size_t)gw * 32 + lane;
    float2 av = *ap;
    av.x += a0; av.y += a1;
    *ap = av;
}

// KL term over all N rows. block = 256 = 4 rows x 64 dims.
__global__ void k_kl(const float* __restrict__ lw, const float* __restrict__ lb) {
    __shared__ float swT[TS * DD];
    __shared__ float sb[DD];
    __shared__ float ss[4][TS];
    int tid = threadIdx.x;
    for (int i = tid; i < TS * DD; i += 256) {
        int d = i >> 5, t = i & 31;
        swT[t * DD + d] = lw[i];
    }
    if (tid < DD) sb[tid] = lb[tid];
    __syncthreads();
    int r = tid >> 6;
    int d = tid & 63;
    int row = blockIdx.x * 4 + r;
    if (row < NN && d < TS) ss[r][d] = softplusf(g_acc[(size_t)row * DD + d]);
    __syncthreads();
    float klv = 0.f;
    if (row < NN) {
        float stdv = sb[d] + 1e-8f;
#pragma unroll
        for (int t = 0; t < TS; t++) stdv += ss[r][t] * swT[t * DD + d];
        float mn = g_acc[(size_t)row * DD + d];
        float kl = -0.5f * (1.f + 2.f * stdv - mn * mn - expf(2.f * stdv));
        if (isfinite(kl)) klv = kl;
    }
    float tot = blkSum256(klv);
    if (tid == 0) atomicAdd(&g_sums[1], tot);
}

// BPR + embedding-reg over B samples; one warp per sample.
__global__ void k_bpr(const float* __restrict__ ue, const float* __restrict__ ie,
                      const int* __restrict__ users, const int* __restrict__ pos,
                      const int* __restrict__ neg) {
    int w = (blockIdx.x * blockDim.x + threadIdx.x) >> 5;
    int lane = threadIdx.x & 31;
    if (w >= BB) return;
    int u = users[w], p = pos[w], n = neg[w];
    const float* au = g_acc + (size_t)u * DD;
    const float* ap = g_acc + (size_t)(N_USERS + p) * DD;
    const float* an = g_acc + (size_t)(N_USERS + n) * DD;
    float ps = 0.f, ns = 0.f, es = 0.f;
#pragma unroll
    for (int j = 0; j < 2; j++) {
        int d = lane + 32 * j;
        float x = au[d];
        ps += x * ap[d];
        ns += x * an[d];
        float a = ue[(size_t)u * DD + d], b = ie[(size_t)p * DD + d], c = ie[(size_t)n * DD + d];
        es += a * a + b * b + c * c;
    }
#pragma unroll
    for (int o = 16; o; o >>= 1) {
        ps += __shfl_down_sync(0xffffffffu, ps, o);
        ns += __shfl_down_sync(0xffffffffu, ns, o);
        es += __shfl_down_sync(0xffffffffu, es, o);
    }
    if (lane == 0) {
        atomicAdd(&g_sums[0], softplusf(ns - ps));
        atomicAdd(&g_sums[2], es);
    }
}

// intent regularizer
__global__ void k_intreg(const float* __restrict__ ui, const float* __restrict__ ii) {
    int i = blockIdx.x * blockDim.x + threadIdx.x;
    float v = 0.f;
    if (i < DD * NI)            { float a = ui[i];           v = a * a; }
    else if (i < 2 * DD * NI)   { float a = ii[i - DD * NI]; v = a * a; }
    float tot = blkSum256(v);
    if (threadIdx.x == 0) atomicAdd(&g_sums[3], tot);
}

// per-sample features: normalized gen/int rows (fp16 out) + fp32 pos diagonal.
__global__ void k_sample(const float* __restrict__ lw, const float* __restrict__ lb,
                         const float* __restrict__ eps,
                         const float* __restrict__ uintm, const float* __restrict__ iintm,
                         const int* __restrict__ users, const int* __restrict__ pos) {
    __shared__ float mrow[DD];
    __shared__ float sp[TS];
    __shared__ float prob[NI];
    __shared__ float partial[4];
    int b = blockIdx.x & (BB - 1);
    int side = blockIdx.x >> 12;
    int tid = threadIdx.x;
    int node = side ? (N_USERS + pos[b]) : users[b];
    const float* intent = side ? iintm : uintm;
    __half* outgen = side ? g_igenh : g_ugenh;
    __half* outint = side ? g_iinth : g_uinth;

    if (tid < DD) mrow[tid] = g_acc[(size_t)node * DD + tid];
    __syncthreads();
    if (tid < TS) sp[tid] = softplusf(mrow[tid]);
    __syncthreads();

    float genv = 0.f;
    if (tid < DD) {
        float stdv = lb[tid] + 1e-8f;
#pragma unroll
        for (int t = 0; t < TS; t++) stdv += sp[t] * lw[tid * TS + t];
        genv = mrow[tid] + eps[(size_t)node * DD + tid] * stdv;
    }
    float gn2 = blkSum128(genv * genv, partial);
    float genn = genv * rsqrtf(gn2);
    if (tid < DD) outgen[b * DD + tid] = __float2half(genn);

    float lg = 0.f;
#pragma unroll
    for (int d = 0; d < DD; d++) lg += mrow[d] * intent[d * NI + tid];
    float mx = blkMax128(lg, partial);
    float ev = expf(lg - mx);
    float ssum = blkSum128(ev, partial);
    prob[tid] = ev;
    __syncthreads();

    float o = 0.f;
    if (tid < DD) {
        const float4* ip = (const float4*)(intent + tid * NI);
        const float4* pp = (const float4*)prob;
#pragma unroll
        for (int k = 0; k < NI / 4; k++) {
            float4 a = ip[k], pq = pp[k];
            o += a.x * pq.x + a.y * pq.y + a.z * pq.z + a.w * pq.w;
        }
        o /= ssum;
    }
    float on2 = blkSum128(o * o, partial);
    float on = o * rsqrtf(on2);
    if (tid < DD) outint[b * DD + tid] = __float2half(on);

    // fp32 diagonal: pos = exp(dot(gen_n, int_n) / T)
    float dot = blkSum128((tid < DD) ? genn * on : 0.f, partial);
    if (tid == 0) g_pos[side * BB + b] = __expf(dot * (1.f / TEMP));
}

// InfoNCE negative sums via HMMA. grid (BB/128, BB/64, 2), block 256 (8 warps).
// Block computes S = e1[i0:i0+128] @ e2[j0:j0+64]^T, accumulates sum_j exp(S/T).
__global__ void k_nce_mma() {
    __shared__ __align__(16) __half As[128 * XS];
    __shared__ __align__(16) __half Bs[64 * XS];
    int z = blockIdx.z;
    const __half* e1 = z ? g_igenh : g_ugenh;
    const __half* e2 = z ? g_iinth : g_uinth;
    float* negbuf = g_neg + z * BB;
    int tid = threadIdx.x;
    int w = tid >> 5, lane = tid & 31;
    int i0 = blockIdx.x * 128, j0 = blockIdx.y * 64;

    // load A: 128 rows x 64 halves (8 x 16B chunks per row), 4 chunks/thread
    {
        const uint4* ga = (const uint4*)(e1 + (size_t)i0 * DD);
#pragma unroll
        for (int q = 0; q < 4; q++) {
            int c = tid + q * 256;
            int row = c >> 3, ch = c & 7;
            *(uint4*)&As[row * XS + ch * 8] = ga[row * 8 + ch];
        }
        const uint4* gb = (const uint4*)(e2 + (size_t)j0 * DD);
#pragma unroll
        for (int q = 0; q < 2; q++) {
            int c = tid + q * 256;
            int row = c >> 3, ch = c & 7;
            *(uint4*)&Bs[row * XS + ch * 8] = gb[row * 8 + ch];
        }
    }
    __syncthreads();

    // A fragments: 4 k-steps, each ldmatrix.x4 (16x16)
    unsigned a[4][4];
#pragma unroll
    for (int ks = 0; ks < 4; ks++) {
        int r = w * 16 + (lane & 15);
        int c = ks * 16 + (lane >> 4) * 8;
        unsigned addr = (unsigned)__cvta_generic_to_shared(&As[r * XS + c]);
        asm volatile("ldmatrix.sync.aligned.m8n8.x4.shared.b16 {%0,%1,%2,%3}, [%4];"
                     : "=r"(a[ks][0]), "=r"(a[ks][1]), "=r"(a[ks][2]), "=r"(a[ks][3])
                     : "r"(addr));
    }

    const float invT = 1.f / TEMP;
    float negs_lo = 0.f, negs_hi = 0.f;
#pragma unroll
    for (int nt = 0; nt < 8; nt++) {
        float c0 = 0.f, c1 = 0.f, c2 = 0.f, c3 = 0.f;
#pragma unroll
        for (int ks = 0; ks < 4; ks++) {
            int br = nt * 8 + (lane & 7);
            int bc = ks * 16 + ((lane >> 3) & 1) * 8;
            unsigned baddr = (unsigned)__cvta_generic_to_shared(&Bs[br * XS + bc]);
            unsigned b0, b1;
            asm volatile("ldmatrix.sync.aligned.m8n8.x2.shared.b16 {%0,%1}, [%2];"
                         : "=r"(b0), "=r"(b1) : "r"(baddr));
            asm volatile("mma.sync.aligned.m16n8k16.row.col.f32.f16.f16.f32 "
                         "{%0,%1,%2,%3}, {%4,%5,%6,%7}, {%8,%9}, {%0,%1,%2,%3};"
                         : "+f"(c0), "+f"(c1), "+f"(c2), "+f"(c3)
                         : "r"(a[ks][0]), "r"(a[ks][1]), "r"(a[ks][2]), "r"(a[ks][3]),
                           "r"(b0), "r"(b1));
        }
        // thread holds: rows (lane/4, lane/4+8), cols 2*(lane%4), +1 of this n-tile
        float sl = __expf(c0 * invT) + __expf(c1 * invT);
        float sh = __expf(c2 * invT) + __expf(c3 * invT);
        sl += __shfl_xor_sync(0xffffffffu, sl, 1);
        sl += __shfl_xor_sync(0xffffffffu, sl, 2);
        sh += __shfl_xor_sync(0xffffffffu, sh, 1);
        sh += __shfl_xor_sync(0xffffffffu, sh, 2);
        negs_lo += sl;
        negs_hi += sh;
    }
    if ((lane & 3) == 0) {
        int r = lane >> 2;
        atomicAdd(&negbuf[i0 + w * 16 + r], negs_lo);
        atomicAdd(&negbuf[i0 + w * 16 + r + 8], negs_hi);
    }
}

// fused nce-final + output (single block of 256)
__global__ void k_final(float* __restrict__ out) {
    int tid = threadIdx.x;
    float cl = 0.f;
    for (int i = tid; i < 2 * BB; i += 256)
        cl += -logf(g_pos[i] / (g_neg[i] + 1e-8f) + 1e-8f);
    float cltot = blkSum256(cl);
    if (tid == 0) {
        float bpr = g_sums[0] / (float)BB;
        float kl  = KL_REG * (g_sums[1] / (float)NN);
        out[0] = bpr + kl;
        out[1] = SSL_REG * (cltot / (float)BB);
        out[2] = EMB_REG * g_sums[2];
        out[3] = INT_REG * g_sums[3];
    }
}

// ---------------- launch ------------------------------------------------------
extern "C" void kernel_launch(void* const* d_in, const int* in_sizes, int n_in,
                              void* d_out, int out_size) {
    const float* user_emb = (const float*)d_in[0];
    const float* item_emb = (const float*)d_in[1];
    const float* uintm    = (const float*)d_in[2];
    const float* iintm    = (const float*)d_in[3];
    const float* lw       = (const float*)d_in[4];
    const float* lb       = (const float*)d_in[5];
    const float* eps      = (const float*)d_in[6];
    const int*   hl       = (const int*)d_in[7];
    const int*   tl       = (const int*)d_in[8];
    const int*   users    = (const int*)d_in[9];
    const int*   pos      = (const int*)d_in[10];
    const int*   neg      = (const int*)d_in[11];
    int E = in_sizes[7];
    float* out = (float*)d_out;

    void *p_cur, *p_nxt;
    cudaGetSymbolAddress(&p_cur, g_curb);
    cudaGetSymbolAddress(&p_nxt, g_nxtb);

    k_clear<<<(NN + 255) / 256, 256>>>();
    k_deg<<<(E + 255) / 256, 256>>>(hl, E);
    k_scanA<<<NBLK_SCAN, 256>>>();
    k_scanB<<<1, 32>>>();
    k_scanC<<<NBLK_SCAN, 256>>>();
    k_scatter<<<(E + 255) / 256, 256>>>(hl, tl, E);
    k_init<<<(NN * (DD / 2) + 255) / 256, 256>>>(user_emb, item_emb);

    k_prop<<<(NN * 32 + 255) / 256, 256>>>((const unsigned*)p_cur, (unsigned*)p_nxt);
    k_prop<<<(NN * 32 + 255) / 256, 256>>>((const unsigned*)p_nxt, (unsigned*)p_cur);
    k_prop<<<(NN * 32 + 255) / 256, 256>>>((const unsigned*)p_cur, (unsigned*)p_nxt);

    k_kl<<<(NN + 3) / 4, 256>>>(lw, lb);
    k_bpr<<<(BB * 32 + 255) / 256, 256>>>(user_emb, item_emb, users, pos, neg);
    k_intreg<<<(2 * DD * NI + 255) / 256, 256>>>(uintm, iintm);
    k_sample<<<2 * BB, 128>>>(lw, lb, eps, uintm, iintm, users, pos);

    {
        dim3 grid(BB / 128, BB / 64, 2);
        k_nce_mma<<<grid, 256>>>();
    }
    k_final<<<1, 256>>>(out);
}